// round 1
// baseline (speedup 1.0000x reference)
#include <cuda_runtime.h>

#define NL 16
#define TSZ (1 << 19)
#define HMASK (TSZ - 1)
#define GROUP 4
#define SPB 48
#define NT (GROUP * SPB)
#define HP1 2654435761u
#define HP2 805459861u

__constant__ float c_scal[NL] = {
    16.f, 22.f, 30.f, 42.f, 58.f, 80.f, 111.f, 153.f,
    212.f, 294.f, 406.f, 561.f, 776.f, 1072.f, 1482.f, 2048.f};

struct SM {
    float w1[2048];      // (32,64) row-major
    float w2[1024];      // (64,16) row-major
    float h1[2048];      // (32,64) row-major
    float h2t[4096];     // (64,64) TRANSPOSED: h2t[j*64+i] = h2[i*64+j]
    float h3[192];       // (64,3)  row-major
    float b1[64], b2[16], hb1[64], hb2[64], hb3[3];
    float Ri[GROUP][9];  // Rinv row-major
    float ti[GROUP][3];
    float d16[GROUP][16];
    float dc[GROUP][64]; // hb1 + d16 @ h1[0:16,:]  (per-batch hoisted)
    float sden[NT];
    float srgb[NT][3];
};

__global__ void __launch_bounds__(NT, 2) nerf_fused_kernel(
    const float* __restrict__ positions, const float* __restrict__ densities,
    const float* __restrict__ normals, const float* __restrict__ c2w,
    const float2* __restrict__ table,
    const float* __restrict__ w1, const float* __restrict__ b1,
    const float* __restrict__ w2, const float* __restrict__ b2,
    const float* __restrict__ h1, const float* __restrict__ hb1,
    const float* __restrict__ h2, const float* __restrict__ hb2,
    const float* __restrict__ h3, const float* __restrict__ hb3,
    float* __restrict__ out)
{
    __shared__ SM s;
    const int tid = threadIdx.x;

    // ---- cooperative weight staging ----
    for (int i = tid; i < 2048; i += NT) s.w1[i] = w1[i];
    for (int i = tid; i < 1024; i += NT) s.w2[i] = w2[i];
    for (int i = tid; i < 2048; i += NT) s.h1[i] = h1[i];
    for (int i = tid; i < 4096; i += NT) {
        int r = i >> 6, c = i & 63;
        s.h2t[c * 64 + r] = h2[i];
    }
    for (int i = tid; i < 192; i += NT) s.h3[i] = h3[i];
    if (tid < 64) { s.b1[tid] = b1[tid]; s.hb1[tid] = hb1[tid]; s.hb2[tid] = hb2[tid]; }
    if (tid < 16) s.b2[tid] = b2[tid];
    if (tid < 3)  s.hb3[tid] = hb3[tid];

    // ---- per-batch setup: Rinv, tinv, SH16(d) ----
    if (tid < GROUP) {
        const int g = tid;
        const int b = blockIdx.x * GROUP + g;
        const float* cw = c2w + b * 12;
        float R00 = cw[0], R01 = cw[1], R02 = cw[2],  t0 = cw[3];
        float R10 = cw[4], R11 = cw[5], R12 = cw[6],  t1 = cw[7];
        float R20 = cw[8], R21 = cw[9], R22 = cw[10], t2 = cw[11];
        // Rinv = R^T
        s.Ri[g][0] = R00; s.Ri[g][1] = R10; s.Ri[g][2] = R20;
        s.Ri[g][3] = R01; s.Ri[g][4] = R11; s.Ri[g][5] = R21;
        s.Ri[g][6] = R02; s.Ri[g][7] = R12; s.Ri[g][8] = R22;
        s.ti[g][0] = -(R00 * t0 + R10 * t1 + R20 * t2);
        s.ti[g][1] = -(R01 * t0 + R11 * t1 + R21 * t2);
        s.ti[g][2] = -(R02 * t0 + R12 * t1 + R22 * t2);
        float n0 = normals[b * 3], n1 = normals[b * 3 + 1], n2 = normals[b * 3 + 2];
        float x = (R00 * n0 + R10 * n1 + R20 * n2 + 1.f) * 0.5f;
        float y = (R01 * n0 + R11 * n1 + R21 * n2 + 1.f) * 0.5f;
        float z = (R02 * n0 + R12 * n1 + R22 * n2 + 1.f) * 0.5f;
        float xx = x * x, yy = y * y, zz = z * z;
        s.d16[g][0]  = 0.28209479177387814f;
        s.d16[g][1]  = -0.48860251190291987f * y;
        s.d16[g][2]  = 0.48860251190291987f * z;
        s.d16[g][3]  = -0.48860251190291987f * x;
        s.d16[g][4]  = 1.0925484305920792f * x * y;
        s.d16[g][5]  = -1.0925484305920792f * y * z;
        s.d16[g][6]  = 0.94617469575756f * zz - 0.31539156525252f;
        s.d16[g][7]  = -1.0925484305920792f * x * z;
        s.d16[g][8]  = 0.5462742152960396f * (xx - yy);
        s.d16[g][9]  = 0.5900435899266435f * y * (3.0f * xx - yy);
        s.d16[g][10] = 2.890611442640554f * x * y * z;
        s.d16[g][11] = 0.4570457994644657f * y * (5.0f * zz - 1.0f);
        s.d16[g][12] = 0.37317633259011546f * z * (5.0f * zz - 3.0f);
        s.d16[g][13] = 0.4570457994644657f * x * (5.0f * zz - 1.0f);
        s.d16[g][14] = 1.445305721320277f * z * (xx - yy);
        s.d16[g][15] = 0.5900435899266435f * x * (xx - 3.0f * yy);
    }
    __syncthreads();

    // ---- per-batch hoisted d16 @ h1[0:16,:] + hb1 ----
    for (int idx = tid; idx < GROUP * 64; idx += NT) {
        int g = idx >> 6, j = idx & 63;
        float a = s.hb1[j];
#pragma unroll
        for (int i = 0; i < 16; i++) a = fmaf(s.d16[g][i], s.h1[i * 64 + j], a);
        s.dc[g][j] = a;
    }
    __syncthreads();

    // ---- per-sample pipeline ----
    const int g = tid / SPB;
    const int sidx = tid - g * SPB;
    const int b = blockIdx.x * GROUP + g;
    const int pt = b * SPB + sidx;

    float p0 = positions[pt * 3], p1 = positions[pt * 3 + 1], p2 = positions[pt * 3 + 2];
    const float* Ri = s.Ri[g];
    float q0 = (Ri[0] * p0 + Ri[1] * p1 + Ri[2] * p2 + s.ti[g][0] + 1.f) * 0.5f;
    float q1 = (Ri[3] * p0 + Ri[4] * p1 + Ri[5] * p2 + s.ti[g][1] + 1.f) * 0.5f;
    float q2 = (Ri[6] * p0 + Ri[7] * p1 + Ri[8] * p2 + s.ti[g][2] + 1.f) * 0.5f;
    bool sel = (q0 > 0.f) && (q0 < 1.f) && (q1 > 0.f) && (q1 < 1.f) && (q2 > 0.f) && (q2 < 1.f);
    float m = sel ? 1.f : 0.f;
    q0 *= m; q1 *= m; q2 *= m;

    // ---- hash encode fused with geo layer-1 ----
    float hid[64];
#pragma unroll
    for (int j = 0; j < 64; j++) hid[j] = s.b1[j];

    for (int l = 0; l < NL; l++) {
        float sc = c_scal[l];
        float sx = q0 * sc, sy = q1 * sc, sz = q2 * sc;
        float fxf = floorf(sx), fyf = floorf(sy), fzf = floorf(sz);
        float ox = sx - fxf, oy = sy - fyf, oz = sz - fzf;
        unsigned fx = (unsigned)fxf, fy = (unsigned)fyf, fz = (unsigned)fzf;
        unsigned cx = (unsigned)ceilf(sx), cy = (unsigned)ceilf(sy), cz = (unsigned)ceilf(sz);
        unsigned yc = cy * HP1, yf = fy * HP1;
        unsigned zc = cz * HP2, zf = fz * HP2;
        const float2* tl = table + (size_t)l * TSZ;
        float2 e0 = __ldg(tl + ((cx ^ yc ^ zc) & HMASK));
        float2 e1 = __ldg(tl + ((cx ^ yf ^ zc) & HMASK));
        float2 e2 = __ldg(tl + ((fx ^ yf ^ zc) & HMASK));
        float2 e3 = __ldg(tl + ((fx ^ yc ^ zc) & HMASK));
        float2 e4 = __ldg(tl + ((cx ^ yc ^ zf) & HMASK));
        float2 e5 = __ldg(tl + ((cx ^ yf ^ zf) & HMASK));
        float2 e6 = __ldg(tl + ((fx ^ yf ^ zf) & HMASK));
        float2 e7 = __ldg(tl + ((fx ^ yc ^ zf) & HMASK));
        float oxm = 1.f - ox, oym = 1.f - oy, ozm = 1.f - oz;
        float a03x = e0.x * ox + e3.x * oxm, a03y = e0.y * ox + e3.y * oxm;
        float a12x = e1.x * ox + e2.x * oxm, a12y = e1.y * ox + e2.y * oxm;
        float a56x = e5.x * ox + e6.x * oxm, a56y = e5.y * ox + e6.y * oxm;
        float a47x = e4.x * ox + e7.x * oxm, a47y = e4.y * ox + e7.y * oxm;
        float b0x = a03x * oy + a12x * oym, b0y = a03y * oy + a12y * oym;
        float b1x = a47x * oy + a56x * oym, b1y = a47y * oy + a56y * oym;
        float ex = b0x * oz + b1x * ozm;
        float ey = b0y * oz + b1y * ozm;
        const float* wr0 = &s.w1[(2 * l) * 64];
        const float* wr1 = &s.w1[(2 * l + 1) * 64];
#pragma unroll
        for (int j = 0; j < 64; j++)
            hid[j] = fmaf(ex, wr0[j], fmaf(ey, wr1[j], hid[j]));
    }
#pragma unroll
    for (int j = 0; j < 64; j++) hid[j] = fmaxf(hid[j], 0.f);

    // ---- geo layer-2: 64 -> 16 ----
    float geo[16];
#pragma unroll
    for (int j = 0; j < 16; j++) geo[j] = s.b2[j];
#pragma unroll
    for (int i = 0; i < 64; i++) {
        float hv = hid[i];
#pragma unroll
        for (int j = 0; j < 16; j++) geo[j] = fmaf(hv, s.w2[i * 16 + j], geo[j]);
    }
#pragma unroll
    for (int j = 0; j < 16; j++) geo[j] = fmaxf(geo[j], 0.f);

    // ---- color layer-1 (geo half; d half hoisted into s.dc) ----
    float g1r[64];
#pragma unroll
    for (int j = 0; j < 64; j++) g1r[j] = s.dc[g][j];
#pragma unroll
    for (int i = 0; i < 16; i++) {
        float gv = geo[i];
#pragma unroll
        for (int j = 0; j < 64; j++) g1r[j] = fmaf(gv, s.h1[(16 + i) * 64 + j], g1r[j]);
    }
#pragma unroll
    for (int j = 0; j < 64; j++) g1r[j] = fmaxf(g1r[j], 0.f);

    // ---- color layer-2 (streamed) + layer-3 ----
    float r0 = s.hb3[0], r1 = s.hb3[1], r2 = s.hb3[2];
    for (int j = 0; j < 64; j++) {
        float t = s.hb2[j];
        const float* hr = &s.h2t[j * 64];
#pragma unroll
        for (int i = 0; i < 64; i++) t = fmaf(g1r[i], hr[i], t);
        t = fmaxf(t, 0.f);
        r0 = fmaf(t, s.h3[j * 3 + 0], r0);
        r1 = fmaf(t, s.h3[j * 3 + 1], r1);
        r2 = fmaf(t, s.h3[j * 3 + 2], r2);
    }
    r0 = 1.f / (1.f + expf(-r0));
    r1 = 1.f / (1.f + expf(-r1));
    r2 = 1.f / (1.f + expf(-r2));

    s.sden[tid] = densities[pt];
    s.srgb[tid][0] = r0; s.srgb[tid][1] = r1; s.srgb[tid][2] = r2;
    __syncthreads();

    // ---- softmax-weighted reduction over samples ----
    if (sidx == 0) {
        const float* dn = &s.sden[g * SPB];
        float mx = -1e30f;
        for (int k = 0; k < SPB; k++) mx = fmaxf(mx, dn[k]);
        float sum = 0.f, a0 = 0.f, a1 = 0.f, a2 = 0.f;
        for (int k = 0; k < SPB; k++) {
            float w = expf(dn[k] - mx);
            sum += w;
            a0 = fmaf(w, s.srgb[g * SPB + k][0], a0);
            a1 = fmaf(w, s.srgb[g * SPB + k][1], a1);
            a2 = fmaf(w, s.srgb[g * SPB + k][2], a2);
        }
        float inv = 1.f / sum;
        out[b * 3 + 0] = a0 * inv;
        out[b * 3 + 1] = a1 * inv;
        out[b * 3 + 2] = a2 * inv;
    }
}

extern "C" void kernel_launch(void* const* d_in, const int* in_sizes, int n_in,
                              void* d_out, int out_size) {
    const float*  positions = (const float*)d_in[0];
    const float*  densities = (const float*)d_in[1];
    const float*  normals   = (const float*)d_in[2];
    const float*  c2w       = (const float*)d_in[3];
    const float2* table     = (const float2*)d_in[4];
    const float*  w1  = (const float*)d_in[5];
    const float*  b1  = (const float*)d_in[6];
    const float*  w2  = (const float*)d_in[7];
    const float*  b2  = (const float*)d_in[8];
    const float*  h1  = (const float*)d_in[9];
    const float*  hb1 = (const float*)d_in[10];
    const float*  h2  = (const float*)d_in[11];
    const float*  hb2 = (const float*)d_in[12];
    const float*  h3  = (const float*)d_in[13];
    const float*  hb3 = (const float*)d_in[14];
    float* out = (float*)d_out;

    const int B = in_sizes[2] / 3;  // normals: (B,3)
    nerf_fused_kernel<<<B / GROUP, NT>>>(
        positions, densities, normals, c2w, table,
        w1, b1, w2, b2, h1, hb1, h2, hb2, h3, hb3, out);
}

// round 2
// speedup vs baseline: 1.7746x; 1.7746x over previous
#include <cuda_runtime.h>

#define NL 16
#define TSZ (1 << 19)
#define HMASK (TSZ - 1)
#define HP1 2654435761u
#define HP2 805459861u
#define BMAX 4096
#define SPB 48
#define NPTS (BMAX * SPB)
#define SROW 196            // smem row stride (192 samples + pad)

__constant__ float c_scal[NL] = {
    16.f, 22.f, 30.f, 42.f, 58.f, 80.f, 111.f, 153.f,
    212.f, 294.f, 406.f, 561.f, 776.f, 1072.f, 1482.f, 2048.f};

// scratch (device globals; no runtime allocation)
__device__ float g_enc[32 * NPTS];   // K-major encoded features
__device__ float g_rt[BMAX * 16];    // per-batch Rinv(9) + tinv(3)
__device__ float g_dc[BMAX * 64];    // per-batch hb1 + d16 @ h1[0:16,:]

// ---------------------------------------------------------------- kernel 0
__global__ void prep_kernel(const float* __restrict__ normals,
                            const float* __restrict__ c2w,
                            const float* __restrict__ h1g,
                            const float* __restrict__ hb1g)
{
    __shared__ float d16[16];
    const int b = blockIdx.x;
    if (threadIdx.x == 0) {
        const float* cw = c2w + b * 12;
        float R00 = cw[0], R01 = cw[1], R02 = cw[2],  t0 = cw[3];
        float R10 = cw[4], R11 = cw[5], R12 = cw[6],  t1 = cw[7];
        float R20 = cw[8], R21 = cw[9], R22 = cw[10], t2 = cw[11];
        float* rt = &g_rt[b * 16];
        rt[0] = R00; rt[1] = R10; rt[2] = R20;
        rt[3] = R01; rt[4] = R11; rt[5] = R21;
        rt[6] = R02; rt[7] = R12; rt[8] = R22;
        rt[9]  = -(R00 * t0 + R10 * t1 + R20 * t2);
        rt[10] = -(R01 * t0 + R11 * t1 + R21 * t2);
        rt[11] = -(R02 * t0 + R12 * t1 + R22 * t2);
        float n0 = normals[b*3], n1 = normals[b*3+1], n2 = normals[b*3+2];
        float x = (R00*n0 + R10*n1 + R20*n2 + 1.f) * 0.5f;
        float y = (R01*n0 + R11*n1 + R21*n2 + 1.f) * 0.5f;
        float z = (R02*n0 + R12*n1 + R22*n2 + 1.f) * 0.5f;
        float xx = x*x, yy = y*y, zz = z*z;
        d16[0]  = 0.28209479177387814f;
        d16[1]  = -0.48860251190291987f * y;
        d16[2]  = 0.48860251190291987f * z;
        d16[3]  = -0.48860251190291987f * x;
        d16[4]  = 1.0925484305920792f * x * y;
        d16[5]  = -1.0925484305920792f * y * z;
        d16[6]  = 0.94617469575756f * zz - 0.31539156525252f;
        d16[7]  = -1.0925484305920792f * x * z;
        d16[8]  = 0.5462742152960396f * (xx - yy);
        d16[9]  = 0.5900435899266435f * y * (3.0f * xx - yy);
        d16[10] = 2.890611442640554f * x * y * z;
        d16[11] = 0.4570457994644657f * y * (5.0f * zz - 1.0f);
        d16[12] = 0.37317633259011546f * z * (5.0f * zz - 3.0f);
        d16[13] = 0.4570457994644657f * x * (5.0f * zz - 1.0f);
        d16[14] = 1.445305721320277f * z * (xx - yy);
        d16[15] = 0.5900435899266435f * x * (xx - 3.0f * yy);
    }
    __syncthreads();
    const int j = threadIdx.x;  // 64 threads
    float a = hb1g[j];
#pragma unroll
    for (int i = 0; i < 16; i++) a = fmaf(d16[i], h1g[i * 64 + j], a);
    g_dc[b * 64 + j] = a;
}

// ---------------------------------------------------------------- kernel A
__global__ void __launch_bounds__(256) enc_kernel(
    const float* __restrict__ positions,
    const float2* __restrict__ table)
{
    const int pt = blockIdx.x * 256 + threadIdx.x;
    const int b = pt / SPB;
    const float* rt = &g_rt[b * 16];
    float p0 = positions[pt*3], p1 = positions[pt*3+1], p2 = positions[pt*3+2];
    float q0 = (rt[0]*p0 + rt[1]*p1 + rt[2]*p2 + rt[9]  + 1.f) * 0.5f;
    float q1 = (rt[3]*p0 + rt[4]*p1 + rt[5]*p2 + rt[10] + 1.f) * 0.5f;
    float q2 = (rt[6]*p0 + rt[7]*p1 + rt[8]*p2 + rt[11] + 1.f) * 0.5f;
    bool sel = (q0 > 0.f) && (q0 < 1.f) && (q1 > 0.f) && (q1 < 1.f) && (q2 > 0.f) && (q2 < 1.f);
    float m = sel ? 1.f : 0.f;
    q0 *= m; q1 *= m; q2 *= m;

    for (int l = 0; l < NL; l++) {
        float sc = c_scal[l];
        float sx = q0 * sc, sy = q1 * sc, sz = q2 * sc;
        float fxf = floorf(sx), fyf = floorf(sy), fzf = floorf(sz);
        float ox = sx - fxf, oy = sy - fyf, oz = sz - fzf;
        unsigned fx = (unsigned)fxf, fy = (unsigned)fyf, fz = (unsigned)fzf;
        unsigned cx = (unsigned)ceilf(sx), cy = (unsigned)ceilf(sy), cz = (unsigned)ceilf(sz);
        unsigned yc = cy * HP1, yf = fy * HP1;
        unsigned zc = cz * HP2, zf = fz * HP2;
        const float2* tl = table + (size_t)l * TSZ;
        float2 e0 = __ldg(tl + ((cx ^ yc ^ zc) & HMASK));
        float2 e1 = __ldg(tl + ((cx ^ yf ^ zc) & HMASK));
        float2 e2 = __ldg(tl + ((fx ^ yf ^ zc) & HMASK));
        float2 e3 = __ldg(tl + ((fx ^ yc ^ zc) & HMASK));
        float2 e4 = __ldg(tl + ((cx ^ yc ^ zf) & HMASK));
        float2 e5 = __ldg(tl + ((cx ^ yf ^ zf) & HMASK));
        float2 e6 = __ldg(tl + ((fx ^ yf ^ zf) & HMASK));
        float2 e7 = __ldg(tl + ((fx ^ yc ^ zf) & HMASK));
        float oxm = 1.f - ox, oym = 1.f - oy, ozm = 1.f - oz;
        float a03x = e0.x*ox + e3.x*oxm, a03y = e0.y*ox + e3.y*oxm;
        float a12x = e1.x*ox + e2.x*oxm, a12y = e1.y*ox + e2.y*oxm;
        float a56x = e5.x*ox + e6.x*oxm, a56y = e5.y*ox + e6.y*oxm;
        float a47x = e4.x*ox + e7.x*oxm, a47y = e4.y*ox + e7.y*oxm;
        float b0x = a03x*oy + a12x*oym, b0y = a03y*oy + a12y*oym;
        float b1x = a47x*oy + a56x*oym, b1y = a47y*oy + a56y*oym;
        g_enc[(2*l + 0) * NPTS + pt] = b0x*oz + b1x*ozm;
        g_enc[(2*l + 1) * NPTS + pt] = b0y*oz + b1y*ozm;
    }
}

// ---------------------------------------------------------------- kernel B
__global__ void __launch_bounds__(192) mlp_kernel(
    const float* __restrict__ densities,
    const float* __restrict__ w1g, const float* __restrict__ b1g,
    const float* __restrict__ w2g, const float* __restrict__ b2g,
    const float* __restrict__ h1g,
    const float* __restrict__ h2g, const float* __restrict__ hb2g,
    const float* __restrict__ h3g, const float* __restrict__ hb3g,
    float* __restrict__ out)
{
    extern __shared__ float smem[];
    float* s1 = smem;                 // 64 x SROW
    float* s2 = smem + 64 * SROW;     // 64 x SROW

    const int tid = threadIdx.x;
    const int tm = tid % 24;          // m-tile: samples tm*8..tm*8+7
    const int tn = tid / 24;          // n-tile
    const int m0 = blockIdx.x * 192;  // 4 batches per block

    // stage enc tile [32][192] (K-major, coalesced)
    for (int k = 0; k < 32; k++)
        s1[k * SROW + tid] = g_enc[k * NPTS + m0 + tid];
    __syncthreads();

    float C[8][8];

    // ---- GEMM1: enc(32) -> hid(64), relu ----
    {
        float4 bv0 = __ldg((const float4*)&b1g[tn * 8]);
        float4 bv1 = __ldg((const float4*)&b1g[tn * 8 + 4]);
        float bj[8] = {bv0.x, bv0.y, bv0.z, bv0.w, bv1.x, bv1.y, bv1.z, bv1.w};
#pragma unroll
        for (int j = 0; j < 8; j++)
#pragma unroll
            for (int i = 0; i < 8; i++) C[j][i] = bj[j];
#pragma unroll 4
        for (int k = 0; k < 32; k++) {
            float4 a0 = *(const float4*)&s1[k * SROW + tm * 8];
            float4 a1 = *(const float4*)&s1[k * SROW + tm * 8 + 4];
            float4 w0 = __ldg((const float4*)&w1g[k * 64 + tn * 8]);
            float4 w1v = __ldg((const float4*)&w1g[k * 64 + tn * 8 + 4]);
            float A8[8] = {a0.x,a0.y,a0.z,a0.w,a1.x,a1.y,a1.z,a1.w};
            float W8[8] = {w0.x,w0.y,w0.z,w0.w,w1v.x,w1v.y,w1v.z,w1v.w};
#pragma unroll
            for (int j = 0; j < 8; j++)
#pragma unroll
                for (int i = 0; i < 8; i++) C[j][i] = fmaf(W8[j], A8[i], C[j][i]);
        }
#pragma unroll
        for (int j = 0; j < 8; j++) {
            int row = tn * 8 + j;
            *(float4*)&s2[row * SROW + tm * 8] = make_float4(
                fmaxf(C[j][0],0.f), fmaxf(C[j][1],0.f), fmaxf(C[j][2],0.f), fmaxf(C[j][3],0.f));
            *(float4*)&s2[row * SROW + tm * 8 + 4] = make_float4(
                fmaxf(C[j][4],0.f), fmaxf(C[j][5],0.f), fmaxf(C[j][6],0.f), fmaxf(C[j][7],0.f));
        }
    }
    __syncthreads();

    // ---- GEMM2: hid(64) -> geo(16), relu ----
    {
        float C2[2][8];
        float2 bv = __ldg((const float2*)&b2g[tn * 2]);
#pragma unroll
        for (int i = 0; i < 8; i++) { C2[0][i] = bv.x; C2[1][i] = bv.y; }
#pragma unroll 4
        for (int k = 0; k < 64; k++) {
            float4 a0 = *(const float4*)&s2[k * SROW + tm * 8];
            float4 a1 = *(const float4*)&s2[k * SROW + tm * 8 + 4];
            float2 w = __ldg((const float2*)&w2g[k * 16 + tn * 2]);
            float A8[8] = {a0.x,a0.y,a0.z,a0.w,a1.x,a1.y,a1.z,a1.w};
#pragma unroll
            for (int i = 0; i < 8; i++) {
                C2[0][i] = fmaf(w.x, A8[i], C2[0][i]);
                C2[1][i] = fmaf(w.y, A8[i], C2[1][i]);
            }
        }
#pragma unroll
        for (int jj = 0; jj < 2; jj++) {
            int row = tn * 2 + jj;
            *(float4*)&s1[row * SROW + tm * 8] = make_float4(
                fmaxf(C2[jj][0],0.f), fmaxf(C2[jj][1],0.f), fmaxf(C2[jj][2],0.f), fmaxf(C2[jj][3],0.f));
            *(float4*)&s1[row * SROW + tm * 8 + 4] = make_float4(
                fmaxf(C2[jj][4],0.f), fmaxf(C2[jj][5],0.f), fmaxf(C2[jj][6],0.f), fmaxf(C2[jj][7],0.f));
        }
    }
    __syncthreads();

    // ---- GEMM3: geo(16) -> color hidden1 (64), init from per-batch dc, relu ----
    {
        const int gb = blockIdx.x * 4 + tm / 6;   // tiles never cross batches (48 = 6*8)
        float4 d0 = __ldg((const float4*)&g_dc[gb * 64 + tn * 8]);
        float4 d1 = __ldg((const float4*)&g_dc[gb * 64 + tn * 8 + 4]);
        float dj[8] = {d0.x,d0.y,d0.z,d0.w,d1.x,d1.y,d1.z,d1.w};
#pragma unroll
        for (int j = 0; j < 8; j++)
#pragma unroll
            for (int i = 0; i < 8; i++) C[j][i] = dj[j];
#pragma unroll 4
        for (int k = 0; k < 16; k++) {
            float4 a0 = *(const float4*)&s1[k * SROW + tm * 8];
            float4 a1 = *(const float4*)&s1[k * SROW + tm * 8 + 4];
            float4 w0 = __ldg((const float4*)&h1g[(16 + k) * 64 + tn * 8]);
            float4 w1v = __ldg((const float4*)&h1g[(16 + k) * 64 + tn * 8 + 4]);
            float A8[8] = {a0.x,a0.y,a0.z,a0.w,a1.x,a1.y,a1.z,a1.w};
            float W8[8] = {w0.x,w0.y,w0.z,w0.w,w1v.x,w1v.y,w1v.z,w1v.w};
#pragma unroll
            for (int j = 0; j < 8; j++)
#pragma unroll
                for (int i = 0; i < 8; i++) C[j][i] = fmaf(W8[j], A8[i], C[j][i]);
        }
#pragma unroll
        for (int j = 0; j < 8; j++) {
            int row = tn * 8 + j;
            *(float4*)&s2[row * SROW + tm * 8] = make_float4(
                fmaxf(C[j][0],0.f), fmaxf(C[j][1],0.f), fmaxf(C[j][2],0.f), fmaxf(C[j][3],0.f));
            *(float4*)&s2[row * SROW + tm * 8 + 4] = make_float4(
                fmaxf(C[j][4],0.f), fmaxf(C[j][5],0.f), fmaxf(C[j][6],0.f), fmaxf(C[j][7],0.f));
        }
    }
    __syncthreads();

    // ---- GEMM4: hidden1(64) -> hidden2(64), +hb2, relu ----
    {
        float4 bv0 = __ldg((const float4*)&hb2g[tn * 8]);
        float4 bv1 = __ldg((const float4*)&hb2g[tn * 8 + 4]);
        float bj[8] = {bv0.x, bv0.y, bv0.z, bv0.w, bv1.x, bv1.y, bv1.z, bv1.w};
#pragma unroll
        for (int j = 0; j < 8; j++)
#pragma unroll
            for (int i = 0; i < 8; i++) C[j][i] = bj[j];
#pragma unroll 4
        for (int k = 0; k < 64; k++) {
            float4 a0 = *(const float4*)&s2[k * SROW + tm * 8];
            float4 a1 = *(const float4*)&s2[k * SROW + tm * 8 + 4];
            float4 w0 = __ldg((const float4*)&h2g[k * 64 + tn * 8]);
            float4 w1v = __ldg((const float4*)&h2g[k * 64 + tn * 8 + 4]);
            float A8[8] = {a0.x,a0.y,a0.z,a0.w,a1.x,a1.y,a1.z,a1.w};
            float W8[8] = {w0.x,w0.y,w0.z,w0.w,w1v.x,w1v.y,w1v.z,w1v.w};
#pragma unroll
            for (int j = 0; j < 8; j++)
#pragma unroll
                for (int i = 0; i < 8; i++) C[j][i] = fmaf(W8[j], A8[i], C[j][i]);
        }
#pragma unroll
        for (int j = 0; j < 8; j++) {
            int row = tn * 8 + j;
            *(float4*)&s1[row * SROW + tm * 8] = make_float4(
                fmaxf(C[j][0],0.f), fmaxf(C[j][1],0.f), fmaxf(C[j][2],0.f), fmaxf(C[j][3],0.f));
            *(float4*)&s1[row * SROW + tm * 8 + 4] = make_float4(
                fmaxf(C[j][4],0.f), fmaxf(C[j][5],0.f), fmaxf(C[j][6],0.f), fmaxf(C[j][7],0.f));
        }
    }
    __syncthreads();

    // ---- final: hidden2 -> rgb(3), sigmoid; per-sample (m = tid) ----
    float r0 = __ldg(&hb3g[0]), r1 = __ldg(&hb3g[1]), r2 = __ldg(&hb3g[2]);
#pragma unroll 8
    for (int j = 0; j < 64; j++) {
        float t = s1[j * SROW + tid];
        r0 = fmaf(t, __ldg(&h3g[j*3+0]), r0);
        r1 = fmaf(t, __ldg(&h3g[j*3+1]), r1);
        r2 = fmaf(t, __ldg(&h3g[j*3+2]), r2);
    }
    r0 = 1.f / (1.f + expf(-r0));
    r1 = 1.f / (1.f + expf(-r1));
    r2 = 1.f / (1.f + expf(-r2));

    float* sden = s2;           // reuse s2 region
    float* srgb = s2 + 192;
    sden[tid] = densities[m0 + tid];
    srgb[tid*3+0] = r0; srgb[tid*3+1] = r1; srgb[tid*3+2] = r2;
    __syncthreads();

    if (tid % SPB == 0) {
        const int g = tid / SPB;
        const float* dn = &sden[g * SPB];
        float mx = -1e30f;
        for (int k = 0; k < SPB; k++) mx = fmaxf(mx, dn[k]);
        float sum = 0.f, a0 = 0.f, a1 = 0.f, a2 = 0.f;
        for (int k = 0; k < SPB; k++) {
            float w = expf(dn[k] - mx);
            sum += w;
            a0 = fmaf(w, srgb[(g*SPB+k)*3+0], a0);
            a1 = fmaf(w, srgb[(g*SPB+k)*3+1], a1);
            a2 = fmaf(w, srgb[(g*SPB+k)*3+2], a2);
        }
        float inv = 1.f / sum;
        const int b = blockIdx.x * 4 + g;
        out[b*3+0] = a0 * inv;
        out[b*3+1] = a1 * inv;
        out[b*3+2] = a2 * inv;
    }
}

// ---------------------------------------------------------------- launch
extern "C" void kernel_launch(void* const* d_in, const int* in_sizes, int n_in,
                              void* d_out, int out_size) {
    const float*  positions = (const float*)d_in[0];
    const float*  densities = (const float*)d_in[1];
    const float*  normals   = (const float*)d_in[2];
    const float*  c2w       = (const float*)d_in[3];
    const float2* table     = (const float2*)d_in[4];
    const float*  w1  = (const float*)d_in[5];
    const float*  b1  = (const float*)d_in[6];
    const float*  w2  = (const float*)d_in[7];
    const float*  b2  = (const float*)d_in[8];
    const float*  h1  = (const float*)d_in[9];
    const float*  hb1 = (const float*)d_in[10];
    const float*  h2  = (const float*)d_in[11];
    const float*  hb2 = (const float*)d_in[12];
    const float*  h3  = (const float*)d_in[13];
    const float*  hb3 = (const float*)d_in[14];
    float* out = (float*)d_out;

    const int B = in_sizes[2] / 3;        // 4096
    const int npts = B * SPB;             // 196608
    const int smem_b = 2 * 64 * SROW * (int)sizeof(float);  // 100352 B

    cudaFuncSetAttribute(mlp_kernel, cudaFuncAttributeMaxDynamicSharedMemorySize, smem_b);

    prep_kernel<<<B, 64>>>(normals, c2w, h1, hb1);
    enc_kernel<<<npts / 256, 256>>>(positions, table);
    mlp_kernel<<<B / 4, 192, smem_b>>>(densities, w1, b1, w2, b2, h1, h2, hb2, h3, hb3, out);
}